// round 5
// baseline (speedup 1.0000x reference)
#include <cuda_runtime.h>
#include <cuda_bf16.h>
#include <cstdint>

#define TOKENS 8192
#define DM 1024
#define DH 4096
#define NE 8
#define NSLOTS (TOKENS * 2)

// GEMM tiling: CTA 128x128x64, 8 warps (2m x 4n), warp tile 64x32, reg-pipelined
#define BM 128
#define BN 128
#define BK 64
#define NSTG 3
#define PITCH 144                        // bytes per smem row (64 bf16 = 128B + 16 pad)
#define OFF_AH 0
#define OFF_AL 18432
#define OFF_BH 36864
#define OFF_BL 55296
#define STAGE_BYTES 73728
#define SMEM_TOTAL (NSTG * STAGE_BYTES)  // 221184

// ---------------- scratch globals ----------------
__device__ __nv_bfloat16 g_xl_hi[(size_t)TOKENS * DM];
__device__ __nv_bfloat16 g_xl_lo[(size_t)TOKENS * DM];
__device__ __nv_bfloat16 g_w1t_hi[(size_t)NE * DH * DM];   // [E][N=DH][K=DM]
__device__ __nv_bfloat16 g_w1t_lo[(size_t)NE * DH * DM];
__device__ __nv_bfloat16 g_w2t_hi[(size_t)NE * DM * DH];   // [E][N=DM][K=DH]
__device__ __nv_bfloat16 g_w2t_lo[(size_t)NE * DM * DH];
__device__ __nv_bfloat16 g_h_hi[(size_t)NSLOTS * DH];
__device__ __nv_bfloat16 g_h_lo[(size_t)NSLOTS * DH];
__device__ float g_o[(size_t)NSLOTS * DM];
__device__ int g_top2[TOKENS];
__device__ int2 g_slots[TOKENS];
__device__ int g_counts[NE];
__device__ int g_offsets[NE];
__device__ int g_cursor[NE];
__device__ int g_tokens[NSLOTS];
__device__ int g_done;

// ---------------- PTX helpers ----------------
__device__ __forceinline__ uint32_t smem_u32(const void* p) {
    uint32_t a;
    asm("{ .reg .u64 t; cvta.to.shared.u64 t, %1; cvt.u32.u64 %0, t; }" : "=r"(a) : "l"(p));
    return a;
}
__device__ __forceinline__ void cp_async16(uint32_t dst, const void* src) {
    asm volatile("cp.async.cg.shared.global [%0], [%1], 16;" :: "r"(dst), "l"(src));
}
__device__ __forceinline__ void cp_commit() { asm volatile("cp.async.commit_group;" ::: "memory"); }
template <int N>
__device__ __forceinline__ void cp_wait() { asm volatile("cp.async.wait_group %0;" :: "n"(N) : "memory"); }

__device__ __forceinline__ void ldsm4(uint32_t* r, uint32_t addr) {
    asm volatile("ldmatrix.sync.aligned.m8n8.x4.shared.b16 {%0,%1,%2,%3}, [%4];"
                 : "=r"(r[0]), "=r"(r[1]), "=r"(r[2]), "=r"(r[3]) : "r"(addr));
}
__device__ __forceinline__ void mma_bf16(float* c, const uint32_t* a, const uint32_t* b) {
    asm volatile(
        "mma.sync.aligned.m16n8k16.row.col.f32.bf16.bf16.f32 "
        "{%0,%1,%2,%3}, {%4,%5,%6,%7}, {%8,%9}, {%0,%1,%2,%3};"
        : "+f"(c[0]), "+f"(c[1]), "+f"(c[2]), "+f"(c[3])
        : "r"(a[0]), "r"(a[1]), "r"(a[2]), "r"(a[3]), "r"(b[0]), "r"(b[1]));
}

// ---------------- kernel 1: cvt xl -> bf16 hi/lo (+ reset counters) ----------------
__global__ void k_cvt_x(const float* __restrict__ x) {
    if (blockIdx.x == 0 && threadIdx.x < NE + 1) {
        if (threadIdx.x < NE) g_counts[threadIdx.x] = 0;
        else g_done = 0;
    }
    size_t i = (size_t)blockIdx.x * blockDim.x + threadIdx.x;
    float v = x[i];
    __nv_bfloat16 h = __float2bfloat16(v);
    g_xl_hi[i] = h;
    g_xl_lo[i] = __float2bfloat16(v - __bfloat162float(h));
}

// ---------------- kernel 2: transpose-convert both weights ----------------
__global__ void k_wt2(const float* __restrict__ W1, const float* __restrict__ W2) {
    __shared__ float t[32][33];
    const int z = blockIdx.z, which = z >> 3, e = z & 7;
    int n0, k0, K, N;
    const float* W;
    __nv_bfloat16 *Ohi, *Olo;
    if (!which) { K = DM; N = DH; n0 = blockIdx.x * 32; k0 = blockIdx.y * 32;
                  W = W1; Ohi = g_w1t_hi; Olo = g_w1t_lo; }
    else        { K = DH; N = DM; k0 = blockIdx.x * 32; n0 = blockIdx.y * 32;
                  W = W2; Ohi = g_w2t_hi; Olo = g_w2t_lo; }
    const float* Wp = W + (size_t)e * K * N;
    const int tx = threadIdx.x, ty = threadIdx.y;
#pragma unroll
    for (int j = 0; j < 4; j++)
        t[ty + j * 8][tx] = Wp[(size_t)(k0 + ty + j * 8) * N + n0 + tx];
    __syncthreads();
#pragma unroll
    for (int j = 0; j < 4; j++) {
        int n = n0 + ty + j * 8;
        float v = t[tx][ty + j * 8];
        __nv_bfloat16 h = __float2bfloat16(v);
        size_t o = ((size_t)e * N + n) * K + k0 + tx;
        Ohi[o] = h;
        Olo[o] = __float2bfloat16(v - __bfloat162float(h));
    }
}

// ---------------- kernel 3: gating + (last block) scan & scatter ----------------
__global__ void k_gating_route(const float* __restrict__ x0, const float* __restrict__ Wg) {
    const int warp = threadIdx.x >> 5, lane = threadIdx.x & 31;
    const int t = blockIdx.x * (blockDim.x >> 5) + warp;
    {
        double acc[NE];
#pragma unroll
        for (int e = 0; e < NE; e++) acc[e] = 0.0;
        const float* x = x0 + (size_t)t * DM;
        for (int k = lane; k < DM; k += 32) {
            float xv = x[k];
            const float4 w0 = *reinterpret_cast<const float4*>(Wg + (size_t)k * NE);
            const float4 w1 = *reinterpret_cast<const float4*>(Wg + (size_t)k * NE + 4);
            acc[0] += (double)xv * w0.x; acc[1] += (double)xv * w0.y;
            acc[2] += (double)xv * w0.z; acc[3] += (double)xv * w0.w;
            acc[4] += (double)xv * w1.x; acc[5] += (double)xv * w1.y;
            acc[6] += (double)xv * w1.z; acc[7] += (double)xv * w1.w;
        }
#pragma unroll
        for (int off = 16; off > 0; off >>= 1)
#pragma unroll
            for (int e = 0; e < NE; e++) acc[e] += __shfl_xor_sync(0xffffffffu, acc[e], off);
        if (lane == 0) {
            int i1 = 0; double v1 = acc[0];
#pragma unroll
            for (int e = 1; e < NE; e++) if (acc[e] > v1) { v1 = acc[e]; i1 = e; }
            int i2 = -1; double v2 = -1.0e300;
#pragma unroll
            for (int e = 0; e < NE; e++) if (e != i1 && acc[e] > v2) { v2 = acc[e]; i2 = e; }
            g_top2[t] = i1 | (i2 << 8);
            atomicAdd(&g_counts[i1], 1);
            atomicAdd(&g_counts[i2], 1);
        }
    }
    __shared__ int isLast;
    __syncthreads();
    if (threadIdx.x == 0) {
        __threadfence();
        isLast = (atomicAdd(&g_done, 1) == (int)gridDim.x - 1) ? 1 : 0;
    }
    __syncthreads();
    if (!isLast) return;
    __threadfence();
    if (threadIdx.x == 0) {
        int s = 0;
        for (int e = 0; e < NE; e++) { g_offsets[e] = s; g_cursor[e] = s; s += g_counts[e]; }
    }
    __syncthreads();
    for (int tk = threadIdx.x; tk < TOKENS; tk += blockDim.x) {
        int p = g_top2[tk];
        int s1 = atomicAdd(&g_cursor[p & 0xff], 1);
        int s2 = atomicAdd(&g_cursor[(p >> 8) & 0xff], 1);
        g_tokens[s1] = tk;
        g_tokens[s2] = tk;
        g_slots[tk] = make_int2(s1, s2);
    }
}

// ---------------- HMMA GEMM inner helpers ----------------
__device__ __forceinline__ void load_ab(uint32_t* ahi, uint32_t* bh, uint32_t st,
                                        uint32_t a_off, uint32_t b_off, int k16) {
    const uint32_t ab = st + OFF_AH + a_off + k16 * 32;
    const uint32_t bb = st + OFF_BH + b_off + k16 * 32;
    ldsm4(ahi + 0,  ab);
    ldsm4(ahi + 4,  ab + 16 * PITCH);
    ldsm4(ahi + 8,  ab + 32 * PITCH);
    ldsm4(ahi + 12, ab + 48 * PITCH);
    ldsm4(bh + 0, bb);
    ldsm4(bh + 4, bb + 16 * PITCH);
}
__device__ __forceinline__ void load_l(uint32_t* alo, uint32_t* bl, uint32_t st,
                                       uint32_t a_off, uint32_t b_off, int k16) {
    const uint32_t ab = st + OFF_AL + a_off + k16 * 32;
    const uint32_t bb = st + OFF_BL + b_off + k16 * 32;
    ldsm4(alo + 0,  ab);
    ldsm4(alo + 4,  ab + 16 * PITCH);
    ldsm4(alo + 8,  ab + 32 * PITCH);
    ldsm4(alo + 12, ab + 48 * PITCH);
    ldsm4(bl + 0, bb);
    ldsm4(bl + 4, bb + 16 * PITCH);
}
__device__ __forceinline__ void pass(float acc[4][4][4], const uint32_t* A, const uint32_t* B) {
#pragma unroll
    for (int mt = 0; mt < 4; mt++)
#pragma unroll
        for (int nt = 0; nt < 4; nt++)
            mma_bf16(acc[mt][nt], A + mt * 4, B + (nt >> 1) * 4 + (nt & 1) * 2);
}

template <int KT, int NTOT, bool IS_G1>
__global__ __launch_bounds__(256, 1) void k_hmma(const float* __restrict__ bias) {
    const int e = blockIdx.z;
    const int cnt = g_counts[e];
    const int m0 = blockIdx.y * BM;
    if (m0 >= cnt) return;
    const int off = g_offsets[e];
    const int n0 = blockIdx.x * BN;
    const int tid = threadIdx.x;

    extern __shared__ char smem[];
    __shared__ int s_rows[BM];
    const uint32_t sb = smem_u32(smem);

    if (tid < BM) {
        int mm = m0 + tid;
        int mc = mm < cnt ? mm : cnt - 1;
        s_rows[tid] = IS_G1 ? g_tokens[off + mc] : (off + mc);
    }
    __syncthreads();

    const __nv_bfloat16* Ahi = IS_G1 ? g_xl_hi : g_h_hi;
    const __nv_bfloat16* Alo = IS_G1 ? g_xl_lo : g_h_lo;
    const __nv_bfloat16* Bhi = (IS_G1 ? g_w1t_hi : g_w2t_hi) + ((size_t)e * NTOT + n0) * KT;
    const __nv_bfloat16* Blo = (IS_G1 ? g_w1t_lo : g_w2t_lo) + ((size_t)e * NTOT + n0) * KT;

    // fill plan: thread t -> row t>>1 (A-gather row & B n-row), half t&1 (64B of the 128B row)
    const int rA = tid >> 1, hf = tid & 1;
    const uint32_t dst0 = (uint32_t)rA * PITCH + hf * 64;
    const __nv_bfloat16* ah  = Ahi + (size_t)s_rows[rA] * KT + hf * 32;
    const __nv_bfloat16* al  = Alo + (size_t)s_rows[rA] * KT + hf * 32;
    const __nv_bfloat16* bhp = Bhi + (size_t)rA * KT + hf * 32;
    const __nv_bfloat16* blp = Blo + (size_t)rA * KT + hf * 32;

#define FILL(sidx, k0_) do {                                                   \
        uint32_t _s = sb + (sidx) * STAGE_BYTES + dst0;                        \
        _Pragma("unroll")                                                      \
        for (int i = 0; i < 4; i++) {                                          \
            cp_async16(_s + OFF_AH + i * 16, ah  + (k0_) + i * 8);             \
            cp_async16(_s + OFF_AL + i * 16, al  + (k0_) + i * 8);             \
            cp_async16(_s + OFF_BH + i * 16, bhp + (k0_) + i * 8);             \
            cp_async16(_s + OFF_BL + i * 16, blp + (k0_) + i * 8);             \
        }                                                                      \
    } while (0)

    const int lane = tid & 31, wid = tid >> 5;
    const int warp_m = wid >> 2, warp_n = wid & 3;
    const uint32_t a_off = (warp_m * 64 + (lane & 15)) * PITCH + (lane >> 4) * 16;
    const uint32_t b_off = (warp_n * 32 + ((lane >> 4) << 3) + (lane & 7)) * PITCH
                           + ((lane >> 3) & 1) * 16;

    float acc[4][4][4];
#pragma unroll
    for (int i = 0; i < 4; i++)
#pragma unroll
        for (int j = 0; j < 4; j++)
#pragma unroll
            for (int q = 0; q < 4; q++) acc[i][j][q] = 0.f;

    uint32_t ahi[2][16], alo[2][16], bhf[2][8], blf[2][8];

    constexpr int NKC = KT / BK;
    FILL(0, 0);  cp_commit();
    FILL(1, BK); cp_commit();

    for (int kc = 0; kc < NKC; kc++) {
        cp_wait<1>();
        __syncthreads();
        if (kc + 2 < NKC) FILL((kc + 2) % NSTG, (kc + 2) * BK);
        cp_commit();
        const uint32_t st = sb + (kc % NSTG) * STAGE_BYTES;
        load_ab(ahi[0], bhf[0], st, a_off, b_off, 0);
        load_l (alo[0], blf[0], st, a_off, b_off, 0);
#pragma unroll
        for (int s = 0; s < 4; s++) {
            const int cur = s & 1, nb = cur ^ 1;
            if (s < 3) load_ab(ahi[nb], bhf[nb], st, a_off, b_off, s + 1);
            pass(acc, ahi[cur], bhf[cur]);                 // Ahi * Bhi
            if (s < 3) load_l(alo[nb], blf[nb], st, a_off, b_off, s + 1);
            pass(acc, ahi[cur], blf[cur]);                 // Ahi * Blo
            pass(acc, alo[cur], bhf[cur]);                 // Alo * Bhi
        }
    }
#undef FILL

    // ---- epilogue ----
    const int g = lane >> 2, c2 = (lane & 3) * 2;
    const float* bp = bias + (size_t)e * NTOT;
#pragma unroll
    for (int mt = 0; mt < 4; mt++) {
#pragma unroll
        for (int nt = 0; nt < 4; nt++) {
            const int n = n0 + warp_n * 32 + nt * 8 + c2;
            const float bv0 = __ldg(bp + n), bv1 = __ldg(bp + n + 1);
#pragma unroll
            for (int h = 0; h < 2; h++) {
                const int m = m0 + warp_m * 64 + mt * 16 + g + h * 8;
                if (m >= cnt) continue;
                float v0 = acc[mt][nt][h * 2 + 0] + bv0;
                float v1 = acc[mt][nt][h * 2 + 1] + bv1;
                if (IS_G1) {
                    v0 = fmaxf(v0, 0.f); v1 = fmaxf(v1, 0.f);
                    __nv_bfloat162 h2 = __floats2bfloat162_rn(v0, v1);
                    __nv_bfloat162 l2 = __floats2bfloat162_rn(
                        v0 - __bfloat162float(h2.x), v1 - __bfloat162float(h2.y));
                    const size_t o = (size_t)(off + m) * DH + n;
                    *reinterpret_cast<uint32_t*>(g_h_hi + o) = *reinterpret_cast<uint32_t*>(&h2);
                    *reinterpret_cast<uint32_t*>(g_h_lo + o) = *reinterpret_cast<uint32_t*>(&l2);
                } else {
                    float2 v = make_float2(v0, v1);
                    *reinterpret_cast<float2*>(g_o + (size_t)(off + m) * DM + n) = v;
                }
            }
        }
    }
}

// ---------------- kernel 6: combine out[t] = g_o[s1] + g_o[s2] ----------------
__global__ void k_combine(float* __restrict__ out) {
    const int i = blockIdx.x * blockDim.x + threadIdx.x;   // float4 index
    const int t = i >> 8, cc = i & 255;
    const int2 s = g_slots[t];
    const float4 a = *reinterpret_cast<const float4*>(g_o + (size_t)s.x * DM + cc * 4);
    const float4 b = *reinterpret_cast<const float4*>(g_o + (size_t)s.y * DM + cc * 4);
    float4 r = make_float4(a.x + b.x, a.y + b.y, a.z + b.z, a.w + b.w);
    *reinterpret_cast<float4*>(out + (size_t)t * DM + cc * 4) = r;
}

// ---------------- launch ----------------
extern "C" void kernel_launch(void* const* d_in, const int* in_sizes, int n_in,
                              void* d_out, int out_size) {
    const float* xl = (const float*)d_in[0];
    const float* x0 = (const float*)d_in[1];
    const float* Wg = (const float*)d_in[2];
    const float* W1 = (const float*)d_in[3];
    const float* b1 = (const float*)d_in[4];
    const float* W2 = (const float*)d_in[5];
    const float* b2 = (const float*)d_in[6];
    float* out = (float*)d_out;

    cudaFuncSetAttribute((const void*)k_hmma<DM, DH, true>,
                         cudaFuncAttributeMaxDynamicSharedMemorySize, SMEM_TOTAL);
    cudaFuncSetAttribute((const void*)k_hmma<DH, DM, false>,
                         cudaFuncAttributeMaxDynamicSharedMemorySize, SMEM_TOTAL);

    k_cvt_x<<<(TOKENS * DM) / 256, 256>>>(xl);
    k_wt2<<<dim3(128, 32, 16), dim3(32, 8)>>>(W1, W2);
    k_gating_route<<<TOKENS / 8, 256>>>(x0, Wg);
    k_hmma<DM, DH, true><<<dim3(DH / BN, TOKENS / BM, NE), 256, SMEM_TOTAL>>>(b1);
    k_hmma<DH, DM, false><<<dim3(DM / BN, TOKENS / BM, NE), 256, SMEM_TOTAL>>>(b2);
    k_combine<<<(TOKENS * DM / 4) / 256, 256>>>(out);
}

// round 6
// speedup vs baseline: 1.5479x; 1.5479x over previous
#include <cuda_runtime.h>
#include <cuda_bf16.h>
#include <cstdint>

#define TOKENS 8192
#define DM 1024
#define DH 4096
#define NE 8
#define NSLOTS (TOKENS * 2)

// GEMM tiling: CTA 128x128x32, 8 warps (2m x 4n), warp tile 64x32
// SMEM: XOR-swizzled 64B rows, no padding. Stage = 4 tensors * 128 rows * 64B = 32KB.
#define BM 128
#define BN 128
#define BK 32
#define NSTG 3
#define OFF_AH 0
#define OFF_AL 8192
#define OFF_BH 16384
#define OFF_BL 24576
#define STAGE_BYTES 32768
#define SMEM_TOTAL (NSTG * STAGE_BYTES)   // 98304 -> 2 CTAs/SM

// ---------------- scratch globals ----------------
__device__ __nv_bfloat16 g_xl_hi[(size_t)TOKENS * DM];
__device__ __nv_bfloat16 g_xl_lo[(size_t)TOKENS * DM];
__device__ __nv_bfloat16 g_w1t_hi[(size_t)NE * DH * DM];   // [E][N=DH][K=DM]
__device__ __nv_bfloat16 g_w1t_lo[(size_t)NE * DH * DM];
__device__ __nv_bfloat16 g_w2t_hi[(size_t)NE * DM * DH];   // [E][N=DM][K=DH]
__device__ __nv_bfloat16 g_w2t_lo[(size_t)NE * DM * DH];
__device__ __nv_bfloat16 g_h_hi[(size_t)NSLOTS * DH];
__device__ __nv_bfloat16 g_h_lo[(size_t)NSLOTS * DH];
__device__ float g_o[(size_t)NSLOTS * DM];
__device__ int g_top2[TOKENS];
__device__ int2 g_slots[TOKENS];
__device__ int g_counts[NE];
__device__ int g_offsets[NE];
__device__ int g_cursor[NE];
__device__ int g_tokens[NSLOTS];
__device__ int g_done;

// ---------------- PTX helpers ----------------
__device__ __forceinline__ uint32_t smem_u32(const void* p) {
    uint32_t a;
    asm("{ .reg .u64 t; cvta.to.shared.u64 t, %1; cvt.u32.u64 %0, t; }" : "=r"(a) : "l"(p));
    return a;
}
__device__ __forceinline__ void cp_async16(uint32_t dst, const void* src) {
    asm volatile("cp.async.cg.shared.global [%0], [%1], 16;" :: "r"(dst), "l"(src));
}
__device__ __forceinline__ void cp_commit() { asm volatile("cp.async.commit_group;" ::: "memory"); }
template <int N>
__device__ __forceinline__ void cp_wait() { asm volatile("cp.async.wait_group %0;" :: "n"(N) : "memory"); }

__device__ __forceinline__ void ldsm4(uint32_t* r, uint32_t addr) {
    asm volatile("ldmatrix.sync.aligned.m8n8.x4.shared.b16 {%0,%1,%2,%3}, [%4];"
                 : "=r"(r[0]), "=r"(r[1]), "=r"(r[2]), "=r"(r[3]) : "r"(addr));
}
__device__ __forceinline__ void mma_bf16(float* c, const uint32_t* a, const uint32_t* b) {
    asm volatile(
        "mma.sync.aligned.m16n8k16.row.col.f32.bf16.bf16.f32 "
        "{%0,%1,%2,%3}, {%4,%5,%6,%7}, {%8,%9}, {%0,%1,%2,%3};"
        : "+f"(c[0]), "+f"(c[1]), "+f"(c[2]), "+f"(c[3])
        : "r"(a[0]), "r"(a[1]), "r"(a[2]), "r"(a[3]), "r"(b[0]), "r"(b[1]));
}

// swizzled offset within a 128x64B tile: row r (0..127), 16B chunk c (0..3)
__device__ __forceinline__ uint32_t swz(int r, int c) {
    return (uint32_t)r * 64u + (uint32_t)((c ^ ((r >> 1) & 3)) << 4);
}

// ---------------- kernel 1: cvt xl -> bf16 hi/lo (+ reset counters) ----------------
__global__ void k_cvt_x(const float* __restrict__ x) {
    if (blockIdx.x == 0 && threadIdx.x < NE + 1) {
        if (threadIdx.x < NE) g_counts[threadIdx.x] = 0;
        else g_done = 0;
    }
    size_t i = (size_t)blockIdx.x * blockDim.x + threadIdx.x;
    float v = x[i];
    __nv_bfloat16 h = __float2bfloat16(v);
    g_xl_hi[i] = h;
    g_xl_lo[i] = __float2bfloat16(v - __bfloat162float(h));
}

// ---------------- kernel 2: transpose-convert both weights ----------------
__global__ void k_wt2(const float* __restrict__ W1, const float* __restrict__ W2) {
    __shared__ float t[32][33];
    const int z = blockIdx.z, which = z >> 3, e = z & 7;
    int n0, k0, K, N;
    const float* W;
    __nv_bfloat16 *Ohi, *Olo;
    if (!which) { K = DM; N = DH; n0 = blockIdx.x * 32; k0 = blockIdx.y * 32;
                  W = W1; Ohi = g_w1t_hi; Olo = g_w1t_lo; }
    else        { K = DH; N = DM; k0 = blockIdx.x * 32; n0 = blockIdx.y * 32;
                  W = W2; Ohi = g_w2t_hi; Olo = g_w2t_lo; }
    const float* Wp = W + (size_t)e * K * N;
    const int tx = threadIdx.x, ty = threadIdx.y;
#pragma unroll
    for (int j = 0; j < 4; j++)
        t[ty + j * 8][tx] = Wp[(size_t)(k0 + ty + j * 8) * N + n0 + tx];
    __syncthreads();
#pragma unroll
    for (int j = 0; j < 4; j++) {
        int n = n0 + ty + j * 8;
        float v = t[tx][ty + j * 8];
        __nv_bfloat16 h = __float2bfloat16(v);
        size_t o = ((size_t)e * N + n) * K + k0 + tx;
        Ohi[o] = h;
        Olo[o] = __float2bfloat16(v - __bfloat162float(h));
    }
}

// ---------------- kernel 3: gating + (last block) scan & scatter ----------------
__global__ void k_gating_route(const float* __restrict__ x0, const float* __restrict__ Wg) {
    const int warp = threadIdx.x >> 5, lane = threadIdx.x & 31;
    const int t = blockIdx.x * (blockDim.x >> 5) + warp;
    {
        double acc[NE];
#pragma unroll
        for (int e = 0; e < NE; e++) acc[e] = 0.0;
        const float* x = x0 + (size_t)t * DM;
        for (int k = lane; k < DM; k += 32) {
            float xv = x[k];
            const float4 w0 = *reinterpret_cast<const float4*>(Wg + (size_t)k * NE);
            const float4 w1 = *reinterpret_cast<const float4*>(Wg + (size_t)k * NE + 4);
            acc[0] += (double)xv * w0.x; acc[1] += (double)xv * w0.y;
            acc[2] += (double)xv * w0.z; acc[3] += (double)xv * w0.w;
            acc[4] += (double)xv * w1.x; acc[5] += (double)xv * w1.y;
            acc[6] += (double)xv * w1.z; acc[7] += (double)xv * w1.w;
        }
#pragma unroll
        for (int off = 16; off > 0; off >>= 1)
#pragma unroll
            for (int e = 0; e < NE; e++) acc[e] += __shfl_xor_sync(0xffffffffu, acc[e], off);
        if (lane == 0) {
            int i1 = 0; double v1 = acc[0];
#pragma unroll
            for (int e = 1; e < NE; e++) if (acc[e] > v1) { v1 = acc[e]; i1 = e; }
            int i2 = -1; double v2 = -1.0e300;
#pragma unroll
            for (int e = 0; e < NE; e++) if (e != i1 && acc[e] > v2) { v2 = acc[e]; i2 = e; }
            g_top2[t] = i1 | (i2 << 8);
            atomicAdd(&g_counts[i1], 1);
            atomicAdd(&g_counts[i2], 1);
        }
    }
    __shared__ int isLast;
    __syncthreads();
    if (threadIdx.x == 0) {
        __threadfence();
        isLast = (atomicAdd(&g_done, 1) == (int)gridDim.x - 1) ? 1 : 0;
    }
    __syncthreads();
    if (!isLast) return;
    __threadfence();
    if (threadIdx.x == 0) {
        int s = 0;
        for (int e = 0; e < NE; e++) { g_offsets[e] = s; g_cursor[e] = s; s += g_counts[e]; }
    }
    __syncthreads();
    for (int tk = threadIdx.x; tk < TOKENS; tk += blockDim.x) {
        int p = g_top2[tk];
        int s1 = atomicAdd(&g_cursor[p & 0xff], 1);
        int s2 = atomicAdd(&g_cursor[(p >> 8) & 0xff], 1);
        g_tokens[s1] = tk;
        g_tokens[s2] = tk;
        g_slots[tk] = make_int2(s1, s2);
    }
}

// ---------------- HMMA GEMM inner loop ----------------
// aoff/boff: lane base offsets (row*64 + swizzled chunk) for k16=0; k16=1 is XOR 32.
__device__ __forceinline__ void compute_stage(uint32_t st, float acc[4][4][4],
                                              uint32_t aoff, uint32_t boff) {
#pragma unroll
    for (int k16 = 0; k16 < 2; k16++) {
        const uint32_t ab = st + OFF_AH + (aoff ^ (k16 << 5));
        const uint32_t bb = st + OFF_BH + (boff ^ (k16 << 5));
        uint32_t af[4][4], bh[2][4], bl[2][4];
#pragma unroll
        for (int mt = 0; mt < 4; mt++) ldsm4(af[mt], ab + mt * 1024);
#pragma unroll
        for (int p = 0; p < 2; p++)   ldsm4(bh[p], bb + p * 1024);
        // pass 1: Ahi * Bhi
#pragma unroll
        for (int mt = 0; mt < 4; mt++)
#pragma unroll
            for (int nt = 0; nt < 4; nt++)
                mma_bf16(acc[mt][nt], af[mt], &bh[nt >> 1][(nt & 1) * 2]);
        // pass 2: Ahi * Blo
#pragma unroll
        for (int p = 0; p < 2; p++)   ldsm4(bl[p], bb + (OFF_BL - OFF_BH) + p * 1024);
#pragma unroll
        for (int mt = 0; mt < 4; mt++)
#pragma unroll
            for (int nt = 0; nt < 4; nt++)
                mma_bf16(acc[mt][nt], af[mt], &bl[nt >> 1][(nt & 1) * 2]);
        // pass 3: Alo * Bhi (reload A frags from lo tile)
#pragma unroll
        for (int mt = 0; mt < 4; mt++) ldsm4(af[mt], ab + (OFF_AL - OFF_AH) + mt * 1024);
#pragma unroll
        for (int mt = 0; mt < 4; mt++)
#pragma unroll
            for (int nt = 0; nt < 4; nt++)
                mma_bf16(acc[mt][nt], af[mt], &bh[nt >> 1][(nt & 1) * 2]);
    }
}

template <int KT, int NTOT, bool IS_G1>
__global__ __launch_bounds__(256, 2) void k_hmma(const float* __restrict__ bias) {
    const int e = blockIdx.z;
    const int cnt = g_counts[e];
    const int m0 = blockIdx.y * BM;
    if (m0 >= cnt) return;
    const int off = g_offsets[e];
    const int n0 = blockIdx.x * BN;
    const int tid = threadIdx.x;

    extern __shared__ char smem[];
    __shared__ int s_rows[BM];
    const uint32_t sb = smem_u32(smem);

    if (tid < BM) {
        int mm = m0 + tid;
        int mc = mm < cnt ? mm : cnt - 1;
        s_rows[tid] = IS_G1 ? g_tokens[off + mc] : (off + mc);
    }
    __syncthreads();

    const __nv_bfloat16* Ahi = IS_G1 ? g_xl_hi : g_h_hi;
    const __nv_bfloat16* Alo = IS_G1 ? g_xl_lo : g_h_lo;
    const __nv_bfloat16* Bhi = (IS_G1 ? g_w1t_hi : g_w2t_hi) + ((size_t)e * NTOT + n0) * KT;
    const __nv_bfloat16* Blo = (IS_G1 ? g_w1t_lo : g_w2t_lo) + ((size_t)e * NTOT + n0) * KT;

    // fill plan: thread -> rows r, r+64; chunk c (16B). Swizzle key identical for r and r+64.
    const int rF = tid >> 2, cF = tid & 3;
    const uint32_t d0 = swz(rF, cF);
    const uint32_t d1 = d0 + 64 * 64;
    const __nv_bfloat16* ah0 = Ahi + (size_t)s_rows[rF] * KT + cF * 8;
    const __nv_bfloat16* al0 = Alo + (size_t)s_rows[rF] * KT + cF * 8;
    const __nv_bfloat16* ah1 = Ahi + (size_t)s_rows[rF + 64] * KT + cF * 8;
    const __nv_bfloat16* al1 = Alo + (size_t)s_rows[rF + 64] * KT + cF * 8;
    const __nv_bfloat16* bh0 = Bhi + (size_t)rF * KT + cF * 8;
    const __nv_bfloat16* bl0 = Blo + (size_t)rF * KT + cF * 8;
    const __nv_bfloat16* bh1 = Bhi + (size_t)(rF + 64) * KT + cF * 8;
    const __nv_bfloat16* bl1 = Blo + (size_t)(rF + 64) * KT + cF * 8;

#define FILL(sidx, k0_) do {                                        \
        uint32_t _s = sb + (sidx) * STAGE_BYTES;                    \
        cp_async16(_s + OFF_AH + d0, ah0 + (k0_));                  \
        cp_async16(_s + OFF_AH + d1, ah1 + (k0_));                  \
        cp_async16(_s + OFF_AL + d0, al0 + (k0_));                  \
        cp_async16(_s + OFF_AL + d1, al1 + (k0_));                  \
        cp_async16(_s + OFF_BH + d0, bh0 + (k0_));                  \
        cp_async16(_s + OFF_BH + d1, bh1 + (k0_));                  \
        cp_async16(_s + OFF_BL + d0, bl0 + (k0_));                  \
        cp_async16(_s + OFF_BL + d1, bl1 + (k0_));                  \
    } while (0)

    // lane ldsm base offsets (k16=0); k16=1 = XOR 32 (swizzle-compatible)
    const int lane = tid & 31, wid = tid >> 5;
    const int warp_m = wid >> 2, warp_n = wid & 3;
    const int rowA = warp_m * 64 + (lane & 15);
    const int rowB = warp_n * 32 + ((lane >> 4) << 3) + (lane & 7);
    const uint32_t aoff = swz(rowA, lane >> 4);
    const uint32_t boff = swz(rowB, (lane >> 3) & 1);

    float acc[4][4][4];
#pragma unroll
    for (int i = 0; i < 4; i++)
#pragma unroll
        for (int j = 0; j < 4; j++)
#pragma unroll
            for (int q = 0; q < 4; q++) acc[i][j][q] = 0.f;

    constexpr int NKC = KT / BK;
    FILL(0, 0);  cp_commit();
    FILL(1, BK); cp_commit();

    for (int kc = 0; kc < NKC; kc++) {
        cp_wait<1>();
        __syncthreads();
        if (kc + 2 < NKC) { FILL((kc + 2) % NSTG, (kc + 2) * BK); }
        cp_commit();
        compute_stage(sb + (kc % NSTG) * STAGE_BYTES, acc, aoff, boff);
    }
#undef FILL

    // ---- epilogue ----
    const int g = lane >> 2, c2 = (lane & 3) * 2;
    const float* bp = bias + (size_t)e * NTOT;
#pragma unroll
    for (int mt = 0; mt < 4; mt++) {
#pragma unroll
        for (int nt = 0; nt < 4; nt++) {
            const int n = n0 + warp_n * 32 + nt * 8 + c2;
            const float bv0 = __ldg(bp + n), bv1 = __ldg(bp + n + 1);
#pragma unroll
            for (int h = 0; h < 2; h++) {
                const int m = m0 + warp_m * 64 + mt * 16 + g + h * 8;
                if (m >= cnt) continue;
                float v0 = acc[mt][nt][h * 2 + 0] + bv0;
                float v1 = acc[mt][nt][h * 2 + 1] + bv1;
                if (IS_G1) {
                    v0 = fmaxf(v0, 0.f); v1 = fmaxf(v1, 0.f);
                    __nv_bfloat162 h2 = __floats2bfloat162_rn(v0, v1);
                    __nv_bfloat162 l2 = __floats2bfloat162_rn(
                        v0 - __bfloat162float(h2.x), v1 - __bfloat162float(h2.y));
                    const size_t o = (size_t)(off + m) * DH + n;
                    *reinterpret_cast<uint32_t*>(g_h_hi + o) = *reinterpret_cast<uint32_t*>(&h2);
                    *reinterpret_cast<uint32_t*>(g_h_lo + o) = *reinterpret_cast<uint32_t*>(&l2);
                } else {
                    float2 v = make_float2(v0, v1);
                    *reinterpret_cast<float2*>(g_o + (size_t)(off + m) * DM + n) = v;
                }
            }
        }
    }
}

// ---------------- kernel 6: combine out[t] = g_o[s1] + g_o[s2] ----------------
__global__ void k_combine(float* __restrict__ out) {
    const int i = blockIdx.x * blockDim.x + threadIdx.x;   // float4 index
    const int t = i >> 8, cc = i & 255;
    const int2 s = g_slots[t];
    const float4 a = *reinterpret_cast<const float4*>(g_o + (size_t)s.x * DM + cc * 4);
    const float4 b = *reinterpret_cast<const float4*>(g_o + (size_t)s.y * DM + cc * 4);
    float4 r = make_float4(a.x + b.x, a.y + b.y, a.z + b.z, a.w + b.w);
    *reinterpret_cast<float4*>(out + (size_t)t * DM + cc * 4) = r;
}

// ---------------- launch ----------------
extern "C" void kernel_launch(void* const* d_in, const int* in_sizes, int n_in,
                              void* d_out, int out_size) {
    const float* xl = (const float*)d_in[0];
    const float* x0 = (const float*)d_in[1];
    const float* Wg = (const float*)d_in[2];
    const float* W1 = (const float*)d_in[3];
    const float* b1 = (const float*)d_in[4];
    const float* W2 = (const float*)d_in[5];
    const float* b2 = (const float*)d_in[6];
    float* out = (float*)d_out;

    cudaFuncSetAttribute((const void*)k_hmma<DM, DH, true>,
                         cudaFuncAttributeMaxDynamicSharedMemorySize, SMEM_TOTAL);
    cudaFuncSetAttribute((const void*)k_hmma<DH, DM, false>,
                         cudaFuncAttributeMaxDynamicSharedMemorySize, SMEM_TOTAL);

    k_cvt_x<<<(TOKENS * DM) / 256, 256>>>(xl);
    k_wt2<<<dim3(128, 32, 16), dim3(32, 8)>>>(W1, W2);
    k_gating_route<<<TOKENS / 8, 256>>>(x0, Wg);
    k_hmma<DM, DH, true><<<dim3(DH / BN, TOKENS / BM, NE), 256, SMEM_TOTAL>>>(b1);
    k_hmma<DH, DM, false><<<dim3(DM / BN, TOKENS / BM, NE), 256, SMEM_TOTAL>>>(b2);
    k_combine<<<(TOKENS * DM / 4) / 256, 256>>>(out);
}

// round 7
// speedup vs baseline: 1.5545x; 1.0043x over previous
#include <cuda_runtime.h>
#include <cuda_bf16.h>
#include <cstdint>

#define TOKENS 8192
#define DM 1024
#define DH 4096
#define NE 8
#define NSLOTS (TOKENS * 2)

// GEMM tiling: CTA 128x128x32, 8 warps (2m x 4n), warp tile 64x32
// SMEM: XOR-swizzled 64B rows, no padding. Stage = 4 tensors * 128 rows * 64B = 32KB.
#define BM 128
#define BN 128
#define BK 32
#define NSTG 3
#define OFF_AH 0
#define OFF_AL 8192
#define OFF_BH 16384
#define OFF_BL 24576
#define STAGE_BYTES 32768
#define SMEM_TOTAL (NSTG * STAGE_BYTES)   // 98304 -> 2 CTAs/SM

// ---------------- scratch globals ----------------
__device__ __nv_bfloat16 g_xl_hi[(size_t)TOKENS * DM];
__device__ __nv_bfloat16 g_xl_lo[(size_t)TOKENS * DM];
__device__ __nv_bfloat16 g_w1t_hi[(size_t)NE * DH * DM];   // [E][N=DH][K=DM]
__device__ __nv_bfloat16 g_w1t_lo[(size_t)NE * DH * DM];
__device__ __nv_bfloat16 g_w2t_hi[(size_t)NE * DM * DH];   // [E][N=DM][K=DH]
__device__ __nv_bfloat16 g_w2t_lo[(size_t)NE * DM * DH];
__device__ __nv_bfloat16 g_h_hi[(size_t)NSLOTS * DH];
__device__ __nv_bfloat16 g_h_lo[(size_t)NSLOTS * DH];
__device__ float g_o[(size_t)NSLOTS * DM];
__device__ int g_top2[TOKENS];
__device__ int2 g_slots[TOKENS];
__device__ int g_counts[NE];
__device__ int g_offsets[NE];
__device__ int g_cursor[NE];
__device__ int g_tokens[NSLOTS];

// ---------------- PTX helpers ----------------
__device__ __forceinline__ uint32_t smem_u32(const void* p) {
    uint32_t a;
    asm("{ .reg .u64 t; cvta.to.shared.u64 t, %1; cvt.u32.u64 %0, t; }" : "=r"(a) : "l"(p));
    return a;
}
__device__ __forceinline__ void cp_async16(uint32_t dst, const void* src) {
    asm volatile("cp.async.cg.shared.global [%0], [%1], 16;" :: "r"(dst), "l"(src));
}
__device__ __forceinline__ void cp_commit() { asm volatile("cp.async.commit_group;" ::: "memory"); }
template <int N>
__device__ __forceinline__ void cp_wait() { asm volatile("cp.async.wait_group %0;" :: "n"(N) : "memory"); }

__device__ __forceinline__ void ldsm4(uint32_t* r, uint32_t addr) {
    asm volatile("ldmatrix.sync.aligned.m8n8.x4.shared.b16 {%0,%1,%2,%3}, [%4];"
                 : "=r"(r[0]), "=r"(r[1]), "=r"(r[2]), "=r"(r[3]) : "r"(addr));
}
__device__ __forceinline__ void mma_bf16(float* c, const uint32_t* a, const uint32_t* b) {
    asm volatile(
        "mma.sync.aligned.m16n8k16.row.col.f32.bf16.bf16.f32 "
        "{%0,%1,%2,%3}, {%4,%5,%6,%7}, {%8,%9}, {%0,%1,%2,%3};"
        : "+f"(c[0]), "+f"(c[1]), "+f"(c[2]), "+f"(c[3])
        : "r"(a[0]), "r"(a[1]), "r"(a[2]), "r"(a[3]), "r"(b[0]), "r"(b[1]));
}

// swizzled offset within a 128x64B tile: row r (0..127), 16B chunk c (0..3)
__device__ __forceinline__ uint32_t swz(int r, int c) {
    return (uint32_t)r * 64u + (uint32_t)((c ^ ((r >> 1) & 3)) << 4);
}

// ---------------- kernel 1: cvt xl -> bf16 hi/lo (+ reset counters) ----------------
__global__ void k_cvt_x(const float* __restrict__ x) {
    if (blockIdx.x == 0 && threadIdx.x < NE) g_counts[threadIdx.x] = 0;
    size_t i = (size_t)blockIdx.x * blockDim.x + threadIdx.x;
    float v = x[i];
    __nv_bfloat16 h = __float2bfloat16(v);
    g_xl_hi[i] = h;
    g_xl_lo[i] = __float2bfloat16(v - __bfloat162float(h));
}

// ---------------- kernel 2: transpose-convert both weights ----------------
__global__ void k_wt2(const float* __restrict__ W1, const float* __restrict__ W2) {
    __shared__ float t[32][33];
    const int z = blockIdx.z, which = z >> 3, e = z & 7;
    int n0, k0, K, N;
    const float* W;
    __nv_bfloat16 *Ohi, *Olo;
    if (!which) { K = DM; N = DH; n0 = blockIdx.x * 32; k0 = blockIdx.y * 32;
                  W = W1; Ohi = g_w1t_hi; Olo = g_w1t_lo; }
    else        { K = DH; N = DM; k0 = blockIdx.x * 32; n0 = blockIdx.y * 32;
                  W = W2; Ohi = g_w2t_hi; Olo = g_w2t_lo; }
    const float* Wp = W + (size_t)e * K * N;
    const int tx = threadIdx.x, ty = threadIdx.y;
#pragma unroll
    for (int j = 0; j < 4; j++)
        t[ty + j * 8][tx] = Wp[(size_t)(k0 + ty + j * 8) * N + n0 + tx];
    __syncthreads();
#pragma unroll
    for (int j = 0; j < 4; j++) {
        int n = n0 + ty + j * 8;
        float v = t[tx][ty + j * 8];
        __nv_bfloat16 h = __float2bfloat16(v);
        size_t o = ((size_t)e * N + n) * K + k0 + tx;
        Ohi[o] = h;
        Olo[o] = __float2bfloat16(v - __bfloat162float(h));
    }
}

// ---------------- kernel 3: gating (top-2 per token, fp64 accumulate) ----------------
__global__ void k_gating(const float* __restrict__ x0, const float* __restrict__ Wg) {
    const int warp = threadIdx.x >> 5, lane = threadIdx.x & 31;
    const int t = blockIdx.x * (blockDim.x >> 5) + warp;
    double acc[NE];
#pragma unroll
    for (int e = 0; e < NE; e++) acc[e] = 0.0;
    const float* x = x0 + (size_t)t * DM;
    for (int k = lane; k < DM; k += 32) {
        float xv = x[k];
        const float4 w0 = *reinterpret_cast<const float4*>(Wg + (size_t)k * NE);
        const float4 w1 = *reinterpret_cast<const float4*>(Wg + (size_t)k * NE + 4);
        acc[0] += (double)xv * w0.x; acc[1] += (double)xv * w0.y;
        acc[2] += (double)xv * w0.z; acc[3] += (double)xv * w0.w;
        acc[4] += (double)xv * w1.x; acc[5] += (double)xv * w1.y;
        acc[6] += (double)xv * w1.z; acc[7] += (double)xv * w1.w;
    }
#pragma unroll
    for (int off = 16; off > 0; off >>= 1)
#pragma unroll
        for (int e = 0; e < NE; e++) acc[e] += __shfl_xor_sync(0xffffffffu, acc[e], off);
    if (lane == 0) {
        int i1 = 0; double v1 = acc[0];
#pragma unroll
        for (int e = 1; e < NE; e++) if (acc[e] > v1) { v1 = acc[e]; i1 = e; }
        int i2 = -1; double v2 = -1.0e300;
#pragma unroll
        for (int e = 0; e < NE; e++) if (e != i1 && acc[e] > v2) { v2 = acc[e]; i2 = e; }
        g_top2[t] = i1 | (i2 << 8);
        atomicAdd(&g_counts[i1], 1);
        atomicAdd(&g_counts[i2], 1);
    }
}

// ---------------- kernel 4: scan (tiny) ----------------
__global__ void k_scan() {
    int s = 0;
    for (int e = 0; e < NE; e++) { g_offsets[e] = s; g_cursor[e] = s; s += g_counts[e]; }
}

// ---------------- kernel 5: parallel scatter ----------------
__global__ void k_scatter() {
    const int t = blockIdx.x * blockDim.x + threadIdx.x;
    const int p = g_top2[t];
    const int s1 = atomicAdd(&g_cursor[p & 0xff], 1);
    const int s2 = atomicAdd(&g_cursor[(p >> 8) & 0xff], 1);
    g_tokens[s1] = t;
    g_tokens[s2] = t;
    g_slots[t] = make_int2(s1, s2);
}

// ---------------- HMMA GEMM inner loop ----------------
__device__ __forceinline__ void compute_stage(uint32_t st, float acc[4][4][4],
                                              uint32_t aoff, uint32_t boff) {
#pragma unroll
    for (int k16 = 0; k16 < 2; k16++) {
        const uint32_t ab = st + OFF_AH + (aoff ^ (k16 << 5));
        const uint32_t bb = st + OFF_BH + (boff ^ (k16 << 5));
        uint32_t af[4][4], bh[2][4], bl[2][4];
#pragma unroll
        for (int mt = 0; mt < 4; mt++) ldsm4(af[mt], ab + mt * 1024);
#pragma unroll
        for (int p = 0; p < 2; p++)   ldsm4(bh[p], bb + p * 1024);
#pragma unroll
        for (int p = 0; p < 2; p++)   ldsm4(bl[p], bb + (OFF_BL - OFF_BH) + p * 1024);
        // pass 1: Ahi * Bhi
#pragma unroll
        for (int mt = 0; mt < 4; mt++)
#pragma unroll
            for (int nt = 0; nt < 4; nt++)
                mma_bf16(acc[mt][nt], af[mt], &bh[nt >> 1][(nt & 1) * 2]);
        // pass 2: Ahi * Blo
#pragma unroll
        for (int mt = 0; mt < 4; mt++)
#pragma unroll
            for (int nt = 0; nt < 4; nt++)
                mma_bf16(acc[mt][nt], af[mt], &bl[nt >> 1][(nt & 1) * 2]);
        // pass 3: Alo * Bhi (reload A frags from lo tile)
#pragma unroll
        for (int mt = 0; mt < 4; mt++) ldsm4(af[mt], ab + (OFF_AL - OFF_AH) + mt * 1024);
#pragma unroll
        for (int mt = 0; mt < 4; mt++)
#pragma unroll
            for (int nt = 0; nt < 4; nt++)
                mma_bf16(acc[mt][nt], af[mt], &bh[nt >> 1][(nt & 1) * 2]);
    }
}

template <int KT, int NTOT, bool IS_G1>
__global__ __launch_bounds__(256, 2) void k_hmma(const float* __restrict__ bias) {
    const int e = blockIdx.z;
    const int cnt = g_counts[e];
    const int m0 = blockIdx.y * BM;
    if (m0 >= cnt) return;
    const int off = g_offsets[e];
    const int n0 = blockIdx.x * BN;
    const int tid = threadIdx.x;

    extern __shared__ char smem[];
    __shared__ int s_rows[BM];
    const uint32_t sb = smem_u32(smem);

    if (tid < BM) {
        int mm = m0 + tid;
        int mc = mm < cnt ? mm : cnt - 1;
        s_rows[tid] = IS_G1 ? g_tokens[off + mc] : (off + mc);
    }
    __syncthreads();

    const __nv_bfloat16* Ahi = IS_G1 ? g_xl_hi : g_h_hi;
    const __nv_bfloat16* Alo = IS_G1 ? g_xl_lo : g_h_lo;
    const __nv_bfloat16* Bhi = (IS_G1 ? g_w1t_hi : g_w2t_hi) + ((size_t)e * NTOT + n0) * KT;
    const __nv_bfloat16* Blo = (IS_G1 ? g_w1t_lo : g_w2t_lo) + ((size_t)e * NTOT + n0) * KT;

    // fill plan: thread -> rows r, r+64; chunk c (16B). Swizzle key identical for r and r+64.
    const int rF = tid >> 2, cF = tid & 3;
    const uint32_t d0 = swz(rF, cF);
    const uint32_t d1 = d0 + 64 * 64;
    const __nv_bfloat16* ah0 = Ahi + (size_t)s_rows[rF] * KT + cF * 8;
    const __nv_bfloat16* al0 = Alo + (size_t)s_rows[rF] * KT + cF * 8;
    const __nv_bfloat16* ah1 = Ahi + (size_t)s_rows[rF + 64] * KT + cF * 8;
    const __nv_bfloat16* al1 = Alo + (size_t)s_rows[rF + 64] * KT + cF * 8;
    const __nv_bfloat16* bh0 = Bhi + (size_t)rF * KT + cF * 8;
    const __nv_bfloat16* bl0 = Blo + (size_t)rF * KT + cF * 8;
    const __nv_bfloat16* bh1 = Bhi + (size_t)(rF + 64) * KT + cF * 8;
    const __nv_bfloat16* bl1 = Blo + (size_t)(rF + 64) * KT + cF * 8;

#define FILL(sidx, k0_) do {                                        \
        uint32_t _s = sb + (sidx) * STAGE_BYTES;                    \
        cp_async16(_s + OFF_AH + d0, ah0 + (k0_));                  \
        cp_async16(_s + OFF_AH + d1, ah1 + (k0_));                  \
        cp_async16(_s + OFF_AL + d0, al0 + (k0_));                  \
        cp_async16(_s + OFF_AL + d1, al1 + (k0_));                  \
        cp_async16(_s + OFF_BH + d0, bh0 + (k0_));                  \
        cp_async16(_s + OFF_BH + d1, bh1 + (k0_));                  \
        cp_async16(_s + OFF_BL + d0, bl0 + (k0_));                  \
        cp_async16(_s + OFF_BL + d1, bl1 + (k0_));                  \
    } while (0)

    const int lane = tid & 31, wid = tid >> 5;
    const int warp_m = wid >> 2, warp_n = wid & 3;
    const int rowA = warp_m * 64 + (lane & 15);
    const int rowB = warp_n * 32 + ((lane >> 4) << 3) + (lane & 7);
    const uint32_t aoff = swz(rowA, lane >> 4);
    const uint32_t boff = swz(rowB, (lane >> 3) & 1);

    float acc[4][4][4];
#pragma unroll
    for (int i = 0; i < 4; i++)
#pragma unroll
        for (int j = 0; j < 4; j++)
#pragma unroll
            for (int q = 0; q < 4; q++) acc[i][j][q] = 0.f;

    constexpr int NKC = KT / BK;
    FILL(0, 0);  cp_commit();
    FILL(1, BK); cp_commit();

    for (int kc = 0; kc < NKC; kc++) {
        cp_wait<1>();
        __syncthreads();
        if (kc + 2 < NKC) { FILL((kc + 2) % NSTG, (kc + 2) * BK); }
        cp_commit();
        compute_stage(sb + (kc % NSTG) * STAGE_BYTES, acc, aoff, boff);
    }
#undef FILL

    // ---- epilogue ----
    const int g = lane >> 2, c2 = (lane & 3) * 2;
    const float* bp = bias + (size_t)e * NTOT;
#pragma unroll
    for (int mt = 0; mt < 4; mt++) {
#pragma unroll
        for (int nt = 0; nt < 4; nt++) {
            const int n = n0 + warp_n * 32 + nt * 8 + c2;
            const float bv0 = __ldg(bp + n), bv1 = __ldg(bp + n + 1);
#pragma unroll
            for (int h = 0; h < 2; h++) {
                const int m = m0 + warp_m * 64 + mt * 16 + g + h * 8;
                if (m >= cnt) continue;
                float v0 = acc[mt][nt][h * 2 + 0] + bv0;
                float v1 = acc[mt][nt][h * 2 + 1] + bv1;
                if (IS_G1) {
                    v0 = fmaxf(v0, 0.f); v1 = fmaxf(v1, 0.f);
                    __nv_bfloat162 h2 = __floats2bfloat162_rn(v0, v1);
                    __nv_bfloat162 l2 = __floats2bfloat162_rn(
                        v0 - __bfloat162float(h2.x), v1 - __bfloat162float(h2.y));
                    const size_t o = (size_t)(off + m) * DH + n;
                    *reinterpret_cast<uint32_t*>(g_h_hi + o) = *reinterpret_cast<uint32_t*>(&h2);
                    *reinterpret_cast<uint32_t*>(g_h_lo + o) = *reinterpret_cast<uint32_t*>(&l2);
                } else {
                    float2 v = make_float2(v0, v1);
                    *reinterpret_cast<float2*>(g_o + (size_t)(off + m) * DM + n) = v;
                }
            }
        }
    }
}

// ---------------- kernel 8: combine out[t] = g_o[s1] + g_o[s2] ----------------
__global__ void k_combine(float* __restrict__ out) {
    const int i = blockIdx.x * blockDim.x + threadIdx.x;   // float4 index
    const int t = i >> 8, cc = i & 255;
    const int2 s = g_slots[t];
    const float4 a = *reinterpret_cast<const float4*>(g_o + (size_t)s.x * DM + cc * 4);
    const float4 b = *reinterpret_cast<const float4*>(g_o + (size_t)s.y * DM + cc * 4);
    float4 r = make_float4(a.x + b.x, a.y + b.y, a.z + b.z, a.w + b.w);
    *reinterpret_cast<float4*>(out + (size_t)t * DM + cc * 4) = r;
}

// ---------------- launch ----------------
extern "C" void kernel_launch(void* const* d_in, const int* in_sizes, int n_in,
                              void* d_out, int out_size) {
    const float* xl = (const float*)d_in[0];
    const float* x0 = (const float*)d_in[1];
    const float* Wg = (const float*)d_in[2];
    const float* W1 = (const float*)d_in[3];
    const float* b1 = (const float*)d_in[4];
    const float* W2 = (const float*)d_in[5];
    const float* b2 = (const float*)d_in[6];
    float* out = (float*)d_out;

    cudaFuncSetAttribute((const void*)k_hmma<DM, DH, true>,
                         cudaFuncAttributeMaxDynamicSharedMemorySize, SMEM_TOTAL);
    cudaFuncSetAttribute((const void*)k_hmma<DH, DM, false>,
                         cudaFuncAttributeMaxDynamicSharedMemorySize, SMEM_TOTAL);

    k_cvt_x<<<(TOKENS * DM) / 256, 256>>>(xl);
    k_wt2<<<dim3(128, 32, 16), dim3(32, 8)>>>(W1, W2);
    k_gating<<<TOKENS / 8, 256>>>(x0, Wg);
    k_scan<<<1, 1>>>();
    k_scatter<<<TOKENS / 256, 256>>>();
    k_hmma<DM, DH, true><<<dim3(DH / BN, TOKENS / BM, NE), 256, SMEM_TOTAL>>>(b1);
    k_hmma<DH, DM, false><<<dim3(DM / BN, TOKENS / BM, NE), 256, SMEM_TOTAL>>>(b2);
    k_combine<<<(TOKENS * DM / 4) / 256, 256>>>(out);
}